// round 11
// baseline (speedup 1.0000x reference)
#include <cuda_runtime.h>
#include <math.h>
#include <stdint.h>

// Problem dims
#define Bz   32
#define Hh   512
#define Ss   128
#define Ee   256
#define Vv   32000
#define G3   1536
#define NT   63
#define KS   4
#define KC   128
#define NB   148

// ---------------- device scratch ----------------
__device__ __align__(256) float d_encW1[Bz*Ss*Hh];
__device__ __align__(256) float d_X    [NT*Bz*Ee];
__device__ __align__(256) float d_gemb [NT*Bz*G3];
__device__ __align__(256) float d_Hall [NT*Bz*Hh];     // [m][k] fp32
__device__ __align__(256) float d_hA   [2*Bz*Hh];
__device__ __align__(256) float d_ctx  [Bz*Hh];
__device__ __align__(256) float d_gxp  [KS*Bz*G3];
__device__ __align__(256) float d_ghzrp[KS*Bz*1024];
__device__ __align__(256) float d_ghhp [KS*Bz*Hh];
__device__ __align__(256) float d_hwp  [KS*Bz*Hh];
__device__ __align__(256) float d_sc   [Bz*Ss];
__device__ unsigned g_cnt;
__device__ unsigned g_gen;

__device__ __forceinline__ float sigmoidf_(float x) { return 1.0f / (1.0f + expf(-x)); }
__device__ __forceinline__ float ftanh(float x) {
    float e = __expf(2.0f * x);
    return 1.0f - __fdividef(2.0f, e + 1.0f);
}

// ---------------- packed f32x2 helpers (Blackwell FFMA2) ----------------
__device__ __forceinline__ unsigned long long bcast2(float x) {
    unsigned long long r; unsigned xi = __float_as_uint(x);
    asm("mov.b64 %0, {%1, %1};" : "=l"(r) : "r"(xi));
    return r;
}
__device__ __forceinline__ void ffma2(unsigned long long& c, unsigned long long a,
                                      unsigned long long b) {
    asm("fma.rn.f32x2 %0, %1, %2, %0;" : "+l"(c) : "l"(a), "l"(b));
}
__device__ __forceinline__ float2 unpack2(unsigned long long v) {
    unsigned lo, hi;
    asm("mov.b64 {%0, %1}, %2;" : "=r"(lo), "=r"(hi) : "l"(v));
    return make_float2(__uint_as_float(lo), __uint_as_float(hi));
}

// ---------------- software grid barrier ----------------
__device__ __forceinline__ void gridbar()
{
    __syncthreads();
    if (threadIdx.x == 0) {
        unsigned g;
        asm volatile("ld.acquire.gpu.u32 %0, [%1];" : "=r"(g) : "l"(&g_gen));
        __threadfence();
        unsigned old = atomicAdd(&g_cnt, 1);
        if (old == NB - 1) {
            g_cnt = 0;
            asm volatile("st.release.gpu.u32 [%0], %1;" :: "l"(&g_gen), "r"(g + 1));
        } else {
            unsigned cur;
            do { asm volatile("ld.acquire.gpu.u32 %0, [%1];" : "=r"(cur) : "l"(&g_gen)); } while (cur == g);
        }
    }
    __syncthreads();
}

// ---------------- token embedding gather ----------------
__global__ void k_tok(const int* __restrict__ dec_input,
                      const int* __restrict__ dec_target,
                      const float* __restrict__ emb)
{
    int row = blockIdx.x;
    int e   = threadIdx.x;
    int i = row >> 5, b = row & 31;
    int tok = (i == 0) ? dec_input[b] : dec_target[b * 64 + i];
    d_X[row * Ee + e] = emb[(size_t)tok * Ee + e];
}

// ---------------- tiled SGEMM with f32x2 inner loop ----------------
// grid: x = M blocks, y = N blocks (M fastest -> B panel reuse in L2)
// mode 0: C[m*N+n];  mode 1: m=t*32+b -> C[(b*NT+t)*N+n]
__global__ __launch_bounds__(256)
void sgemm128(const float* __restrict__ A, const float* __restrict__ B,
              const float* __restrict__ bias, float* __restrict__ C,
              int M, int N, int K, int mode)
{
    __shared__ __align__(16) float As[16][128];
    __shared__ __align__(16) float Bs[16][128];
    int tid = threadIdx.x;
    int tx = tid & 15, ty = tid >> 4;
    int m0 = blockIdx.x * 128;
    int n0 = blockIdx.y * 128;

    unsigned long long acc2[8][4];
    #pragma unroll
    for (int i = 0; i < 8; i++)
        #pragma unroll
        for (int j = 0; j < 4; j++) acc2[i][j] = 0ULL;

    for (int kk = 0; kk < K; kk += 16) {
        #pragma unroll
        for (int l = 0; l < 2; l++) {
            int e  = tid + l * 256;
            int m  = e >> 2;
            int kq = (e & 3) * 4;
            float4 v = make_float4(0.f, 0.f, 0.f, 0.f);
            int gm = m0 + m;
            if (gm < M)
                v = *reinterpret_cast<const float4*>(A + (size_t)gm * K + kk + kq);
            As[kq + 0][m] = v.x; As[kq + 1][m] = v.y;
            As[kq + 2][m] = v.z; As[kq + 3][m] = v.w;
        }
        #pragma unroll
        for (int l = 0; l < 2; l++) {
            int e  = tid + l * 256;
            int k  = e >> 5;
            int nq = (e & 31) * 4;
            float4 v = *reinterpret_cast<const float4*>(B + (size_t)(kk + k) * N + n0 + nq);
            *reinterpret_cast<float4*>(&Bs[k][nq]) = v;
        }
        __syncthreads();
        #pragma unroll
        for (int k = 0; k < 16; k++) {
            float a[8];
            *reinterpret_cast<float4*>(a)     = *reinterpret_cast<const float4*>(&As[k][ty * 8]);
            *reinterpret_cast<float4*>(a + 4) = *reinterpret_cast<const float4*>(&As[k][ty * 8 + 4]);
            ulonglong2 b0 = *reinterpret_cast<const ulonglong2*>(&Bs[k][tx * 8]);
            ulonglong2 b1 = *reinterpret_cast<const ulonglong2*>(&Bs[k][tx * 8 + 4]);
            #pragma unroll
            for (int i = 0; i < 8; i++) {
                unsigned long long ai = bcast2(a[i]);
                ffma2(acc2[i][0], ai, b0.x);
                ffma2(acc2[i][1], ai, b0.y);
                ffma2(acc2[i][2], ai, b1.x);
                ffma2(acc2[i][3], ai, b1.y);
            }
        }
        __syncthreads();
    }

    #pragma unroll
    for (int i = 0; i < 8; i++) {
        int gm = m0 + ty * 8 + i;
        if (gm >= M) continue;
        float* crow;
        if (mode == 0) crow = C + (size_t)gm * N;
        else {
            int t = gm >> 5, b = gm & 31;
            crow = C + ((size_t)b * NT + t) * N;
        }
        float2 p0 = unpack2(acc2[i][0]);
        float2 p1 = unpack2(acc2[i][1]);
        float2 p2 = unpack2(acc2[i][2]);
        float2 p3 = unpack2(acc2[i][3]);
        int n = n0 + tx * 8;
        float4 v0, v1;
        v0.x = p0.x; v0.y = p0.y; v0.z = p1.x; v0.w = p1.y;
        v1.x = p2.x; v1.y = p2.y; v1.z = p3.x; v1.w = p3.y;
        if (bias) {
            v0.x += bias[n + 0]; v0.y += bias[n + 1]; v0.z += bias[n + 2]; v0.w += bias[n + 3];
            v1.x += bias[n + 4]; v1.y += bias[n + 5]; v1.z += bias[n + 6]; v1.w += bias[n + 7];
        }
        *reinterpret_cast<float4*>(crow + n)     = v0;
        *reinterpret_cast<float4*>(crow + n + 4) = v1;
    }
}

// ================= persistent recurrence phases =================
// staged activations in SM[k*36 + b]

__device__ __forceinline__ void phaseA(float* SM, const float* __restrict__ Wx,
                                       const float* __restrict__ Wh,
                                       const float* __restrict__ hcur)
{
    for (int u = blockIdx.x; u < 160; u += NB) {
        int p = u % 40, ks = u / 40;
        int k0 = ks * KC;
        const float* src = (p < 24) ? d_ctx : hcur;
        __syncthreads();
        for (int idx = threadIdx.x; idx < 32 * KC; idx += 256) {
            int k = idx & (KC - 1), b = idx >> 7;
            SM[k * 36 + b] = src[b * Hh + k0 + k];
        }
        __syncthreads();
        int c  = threadIdx.x & 63;
        int bg = (threadIdx.x >> 6) * 8;
        unsigned long long acc2[4] = {0ULL, 0ULL, 0ULL, 0ULL};
        const float* Wp; float* outp; int ldo;
        if (p < 24) {
            int j = p * 64 + c;
            Wp = Wx + (size_t)k0 * G3 + j;
            outp = d_gxp + ks * (Bz * G3) + j; ldo = G3;
        } else {
            int j = (p - 24) * 64 + c;
            Wp = Wh + (size_t)k0 * G3 + j;
            outp = d_ghzrp + ks * (Bz * 1024) + j; ldo = 1024;
        }
        #pragma unroll 4
        for (int k = 0; k < KC; k++) {
            float w = Wp[(size_t)k * G3];
            ulonglong2 p0 = *reinterpret_cast<const ulonglong2*>(SM + k * 36 + bg);
            ulonglong2 p1 = *reinterpret_cast<const ulonglong2*>(SM + k * 36 + bg + 4);
            unsigned long long w2 = bcast2(w);
            ffma2(acc2[0], w2, p0.x);
            ffma2(acc2[1], w2, p0.y);
            ffma2(acc2[2], w2, p1.x);
            ffma2(acc2[3], w2, p1.y);
        }
        #pragma unroll
        for (int q = 0; q < 4; q++) {
            float2 r = unpack2(acc2[q]);
            outp[(bg + q * 2 + 0) * ldo] = r.x;
            outp[(bg + q * 2 + 1) * ldo] = r.y;
        }
    }
}

__device__ __forceinline__ void phaseB(float* SM, const float* __restrict__ Wh,
                                       const float* __restrict__ hcur, int step)
{
    int u = blockIdx.x;
    if (u >= 32) return;
    int p = u & 7, ks = u >> 3;
    int k0 = ks * KC;
    __syncthreads();
    for (int idx = threadIdx.x; idx < 32 * KC; idx += 256) {
        int k = idx & (KC - 1), b = idx >> 7;
        int kk = k0 + k;
        float gxr = d_gemb[(size_t)(step * 32 + b) * G3 + 512 + kk];
        #pragma unroll
        for (int s = 0; s < KS; s++) gxr += d_gxp[s * (Bz * G3) + b * G3 + 512 + kk];
        float ghr = 0.0f;
        #pragma unroll
        for (int s = 0; s < KS; s++) ghr += d_ghzrp[s * (Bz * 1024) + b * 1024 + 512 + kk];
        float r = sigmoidf_(gxr + ghr);
        SM[k * 36 + b] = r * hcur[b * Hh + kk];
    }
    __syncthreads();
    int c  = threadIdx.x & 63;
    int bg = (threadIdx.x >> 6) * 8;
    int j  = p * 64 + c;
    const float* Wp = Wh + (size_t)k0 * G3 + 1024 + j;
    unsigned long long acc2[4] = {0ULL, 0ULL, 0ULL, 0ULL};
    #pragma unroll 4
    for (int k = 0; k < KC; k++) {
        float w = Wp[(size_t)k * G3];
        ulonglong2 p0 = *reinterpret_cast<const ulonglong2*>(SM + k * 36 + bg);
        ulonglong2 p1 = *reinterpret_cast<const ulonglong2*>(SM + k * 36 + bg + 4);
        unsigned long long w2 = bcast2(w);
        ffma2(acc2[0], w2, p0.x);
        ffma2(acc2[1], w2, p0.y);
        ffma2(acc2[2], w2, p1.x);
        ffma2(acc2[3], w2, p1.y);
    }
    float* outp = d_ghhp + ks * (Bz * Hh) + j;
    #pragma unroll
    for (int q = 0; q < 4; q++) {
        float2 r = unpack2(acc2[q]);
        outp[(bg + q * 2 + 0) * Hh] = r.x;
        outp[(bg + q * 2 + 1) * Hh] = r.y;
    }
}

__device__ __forceinline__ void phaseUW2(float* SM, const float* __restrict__ W2,
                                         const float* __restrict__ hcur,
                                         float* __restrict__ hnxt,
                                         float* __restrict__ out,
                                         int step, int upd, int last)
{
    int u = blockIdx.x;
    if (u >= 32) return;
    int p = u & 7, ks = u >> 3;
    int k0 = ks * KC;
    __syncthreads();
    for (int idx = threadIdx.x; idx < 32 * KC; idx += 256) {
        int k = idx & (KC - 1), b = idx >> 7;
        int j = k0 + k;
        float hn;
        if (upd) {
            size_t gbase = (size_t)(step * 32 + b) * G3;
            float gz = d_gemb[gbase + j];
            float gh = d_gemb[gbase + 1024 + j];
            #pragma unroll
            for (int s = 0; s < KS; s++) {
                gz += d_gxp[s * (Bz * G3) + b * G3 + j];
                gh += d_gxp[s * (Bz * G3) + b * G3 + 1024 + j];
            }
            float zr = 0.0f, hhs = 0.0f;
            #pragma unroll
            for (int s = 0; s < KS; s++) {
                zr  += d_ghzrp[s * (Bz * 1024) + b * 1024 + j];
                hhs += d_ghhp [s * (Bz * Hh)   + b * Hh   + j];
            }
            float z  = sigmoidf_(gz + zr);
            float hh = tanhf(gh + hhs);
            hn = z * hcur[b * Hh + j] + (1.0f - z) * hh;
            if (p == 0) {
                hnxt[b * Hh + j] = hn;
                d_Hall[(size_t)(step * 32 + b) * Hh + j] = hn;
                if (last) out[(size_t)Bz * NT * Vv + b * Hh + j] = hn;
            }
        } else {
            hn = hcur[b * Hh + j];
        }
        SM[k * 36 + b] = hn;
    }
    __syncthreads();
    if (last) return;
    int c  = threadIdx.x & 63;
    int bg = (threadIdx.x >> 6) * 8;
    int j2 = p * 64 + c;
    unsigned long long acc2[4] = {0ULL, 0ULL, 0ULL, 0ULL};
    #pragma unroll 4
    for (int k = 0; k < KC; k++) {
        float w = W2[(size_t)(k0 + k) * Hh + j2];
        ulonglong2 p0 = *reinterpret_cast<const ulonglong2*>(SM + k * 36 + bg);
        ulonglong2 p1 = *reinterpret_cast<const ulonglong2*>(SM + k * 36 + bg + 4);
        unsigned long long w2 = bcast2(w);
        ffma2(acc2[0], w2, p0.x);
        ffma2(acc2[1], w2, p0.y);
        ffma2(acc2[2], w2, p1.x);
        ffma2(acc2[3], w2, p1.y);
    }
    #pragma unroll
    for (int q = 0; q < 4; q++) {
        float2 r = unpack2(acc2[q]);
        d_hwp[ks * (Bz * Hh) + (bg + q * 2 + 0) * Hh + j2] = r.x;
        d_hwp[ks * (Bz * Hh) + (bg + q * 2 + 1) * Hh + j2] = r.y;
    }
}

__device__ __forceinline__ void phaseD(float* SM, const float* __restrict__ va)
{
    int u = blockIdx.x;
    if (u >= 128) return;
    int b = u >> 2, ch = u & 3;
    __syncthreads();
    for (int a = threadIdx.x; a < 512; a += 256) {
        float s_ = 0.0f;
        #pragma unroll
        for (int s = 0; s < KS; s++) s_ += d_hwp[s * (Bz * Hh) + b * Hh + a];
        SM[a] = s_;
        SM[512 + a] = va[a];
    }
    __syncthreads();
    int wi = threadIdx.x >> 5, lane = threadIdx.x & 31;
    int sg = lane >> 3, li = lane & 7;
    int s = ch * 32 + wi * 4 + sg;
    const float4* e1 = reinterpret_cast<const float4*>(d_encW1 + ((size_t)(b * Ss + s)) * Hh);
    float part = 0.0f;
    #pragma unroll 4
    for (int it = 0; it < 16; it++) {
        int a4 = li + it * 8;
        float4 v = e1[a4];
        int a = a4 * 4;
        part += ftanh(v.x + SM[a + 0]) * SM[512 + a + 0];
        part += ftanh(v.y + SM[a + 1]) * SM[512 + a + 1];
        part += ftanh(v.z + SM[a + 2]) * SM[512 + a + 2];
        part += ftanh(v.w + SM[a + 3]) * SM[512 + a + 3];
    }
    part += __shfl_down_sync(0xffffffff, part, 4, 8);
    part += __shfl_down_sync(0xffffffff, part, 2, 8);
    part += __shfl_down_sync(0xffffffff, part, 1, 8);
    if (li == 0) d_sc[b * Ss + s] = part;
}

__device__ __forceinline__ void phaseE(float* SM, const float* __restrict__ enc)
{
    int b = blockIdx.x;
    if (b >= 32) return;
    __shared__ float s_mx, s_sum;
    int tid = threadIdx.x;
    float* sc  = SM;
    float* red = SM + 512;
    __syncthreads();
    if (tid < 128) sc[tid] = d_sc[b * Ss + tid];
    __syncthreads();
    red[tid] = (tid < 128) ? sc[tid] : -1e30f;
    __syncthreads();
    for (int st = 128; st > 0; st >>= 1) {
        if (tid < st) red[tid] = fmaxf(red[tid], red[tid + st]);
        __syncthreads();
    }
    if (tid == 0) s_mx = red[0];
    __syncthreads();
    float e = 0.0f;
    if (tid < 128) e = __expf(sc[tid] - s_mx);
    red[tid] = e;
    __syncthreads();
    for (int st = 128; st > 0; st >>= 1) {
        if (tid < st) red[tid] += red[tid + st];
        __syncthreads();
    }
    if (tid == 0) s_sum = red[0];
    __syncthreads();
    // pre-packed softmax pairs {v, v} at SM[768]
    if (tid < 128) {
        float v = e / s_sum;
        *reinterpret_cast<unsigned long long*>(&SM[768 + tid * 2]) = bcast2(v);
    }
    __syncthreads();
    // ctx: each thread owns column pair (2t, 2t+1)
    {
        unsigned long long acc = 0ULL;
        const float* ep = enc + ((size_t)b * Ss) * Hh + 2 * tid;
        const unsigned long long* scp = reinterpret_cast<const unsigned long long*>(&SM[768]);
        #pragma unroll 4
        for (int s2 = 0; s2 < 128; s2++)
            ffma2(acc, scp[s2], *reinterpret_cast<const unsigned long long*>(ep + (size_t)s2 * Hh));
        float2 r = unpack2(acc);
        d_ctx[b * Hh + 2 * tid]     = r.x;
        d_ctx[b * Hh + 2 * tid + 1] = r.y;
    }
}

__global__ __launch_bounds__(256, 1)
void k_persist(const float* __restrict__ dec_hidden, const float* __restrict__ enc,
               const float* __restrict__ va, const float* __restrict__ Wx,
               const float* __restrict__ Wh, const float* __restrict__ W2,
               float* __restrict__ out)
{
    __shared__ __align__(16) float SM[4640];

    if (blockIdx.x < 32) {
        int b = blockIdx.x;
        for (int j = threadIdx.x; j < Hh; j += 256)
            d_hA[b * Hh + j] = dec_hidden[b * Hh + j];
    }
    gridbar();
    phaseUW2(SM, W2, d_hA, d_hA, out, 0, 0, 0);
    gridbar();
    phaseD(SM, va);
    gridbar();
    phaseE(SM, enc);
    gridbar();

    for (int i = 0; i < NT; i++) {
        const float* hcur = d_hA + (i & 1) * (Bz * Hh);
        float* hnxt = d_hA + ((i + 1) & 1) * (Bz * Hh);
        phaseA(SM, Wx, Wh, hcur);
        gridbar();
        phaseB(SM, Wh, hcur, i);
        gridbar();
        phaseUW2(SM, W2, hcur, hnxt, out, i, 1, i == NT - 1);
        gridbar();
        if (i < NT - 1) {
            phaseD(SM, va);
            gridbar();
            phaseE(SM, enc);
            gridbar();
        }
    }
}

// ---------------- launch ----------------
extern "C" void kernel_launch(void* const* d_in, const int* in_sizes, int n_in,
                              void* d_out, int out_size)
{
    const int*   dec_input  = (const int*)  d_in[0];
    const float* dec_hidden = (const float*)d_in[1];
    const float* enc        = (const float*)d_in[2];
    const int*   dec_target = (const int*)  d_in[3];
    const float* emb        = (const float*)d_in[4];
    const float* W1         = (const float*)d_in[5];
    const float* W2         = (const float*)d_in[6];
    const float* va         = (const float*)d_in[7];
    const float* Wx         = (const float*)d_in[8];
    const float* Wh         = (const float*)d_in[9];
    const float* bg         = (const float*)d_in[10];
    const float* Wo         = (const float*)d_in[11];
    const float* bo         = (const float*)d_in[12];
    float* out = (float*)d_out;
    (void)in_sizes; (void)n_in; (void)out_size;

    float *pX, *pEncW1, *pGemb, *pHall;
    cudaGetSymbolAddress((void**)&pX,     d_X);
    cudaGetSymbolAddress((void**)&pEncW1, d_encW1);
    cudaGetSymbolAddress((void**)&pGemb,  d_gemb);
    cudaGetSymbolAddress((void**)&pHall,  d_Hall);

    // kernels 1..3
    k_tok<<<NT * Bz, Ee>>>(dec_input, dec_target, emb);
    // encW1 = enc @ W1 : M=4096, N=512, K=512   (grid x=M blocks, y=N blocks)
    sgemm128<<<dim3(32, 4), 256>>>(enc, W1, nullptr, pEncW1, 4096, 512, 512, 0);
    // gemb = X @ Wx[512:,:] + b_g : M=2016, N=1536, K=256
    sgemm128<<<dim3(16, 12), 256>>>(pX, Wx + 512 * G3, bg, pGemb, 2016, 1536, 256, 0);

    // 4: entire recurrence (ncu profiles this)
    k_persist<<<NB, 256>>>(dec_hidden, enc, va, Wx, Wh, W2, out);

    // 5: preds = Hall @ Wo + bo (fp32, f32x2 pipe), remapped to [B, 63, V]
    sgemm128<<<dim3(16, 250), 256>>>(pHall, Wo, bo, out, 2016, Vv, 512, 1);
}